// round 12
// baseline (speedup 1.0000x reference)
#include <cuda_runtime.h>
#include <cuda_fp16.h>
#include <cstdint>

// ---------------- problem constants ----------------
#define Nb   8
#define LQ   2048
#define Cc   256
#define NQ   (Nb*LQ)        // 16384
#define Ssum 3840
#define NROWS_VAL (Nb*Ssum) // 30720

__device__ __constant__ int   c_T[4]    = {2048, 1024, 512, 256};
__device__ __constant__ int   c_S[4]    = {0, 2048, 3072, 3584};
__device__ __constant__ float c_invT[4] = {1.f/2048.f, 1.f/1024.f, 1.f/512.f, 1.f/256.f};

// ---------------- static scratch ----------------
__device__ float  g_value[NROWS_VAL * Cc];      // fp32 value projection (31.5 MB)
__device__ float  g_offattn[NQ * Cc];           // off logits (0-127) + attn logits (128-255)
__device__ __half g_ah[NROWS_VAL * Cc];         // input_flatten hi
__device__ __half g_al[NROWS_VAL * Cc];         // input_flatten lo
__device__ __half g_qh[NQ * Cc];                // query hi
__device__ __half g_ql[NQ * Cc];                // query lo
__device__ __half g_th[NQ * Cc];                // sampled hi
__device__ __half g_tl[NQ * Cc];                // sampled lo
__device__ __half g_wh[4][Cc * Cc];             // transposed weight hi: 0=val, 1,2=off||attn, 3=out
__device__ __half g_wl[4][Cc * Cc];
__device__ float  g_loc_s[NQ * 8 * 16];
__device__ float  g_attn_s[NQ * 8 * 16];

// ---------------- helpers ----------------
__device__ __forceinline__ uint32_t smem_u32(const void* p) {
    uint32_t a;
    asm("{ .reg .u64 t; cvta.to.shared.u64 t, %1; cvt.u32.u64 %0, t; }" : "=r"(a) : "l"(p));
    return a;
}
__device__ __forceinline__ void ldmatrix_x4(uint32_t& r0, uint32_t& r1, uint32_t& r2, uint32_t& r3,
                                            uint32_t addr) {
    asm volatile("ldmatrix.sync.aligned.m8n8.x4.shared.b16 {%0,%1,%2,%3}, [%4];"
                 : "=r"(r0), "=r"(r1), "=r"(r2), "=r"(r3) : "r"(addr));
}
__device__ __forceinline__ void mma16816(float* c, const uint32_t* a, uint32_t b0, uint32_t b1) {
    asm volatile("mma.sync.aligned.m16n8k16.row.col.f32.f16.f16.f32 "
                 "{%0,%1,%2,%3},{%4,%5,%6,%7},{%8,%9},{%0,%1,%2,%3};"
                 : "+f"(c[0]), "+f"(c[1]), "+f"(c[2]), "+f"(c[3])
                 : "r"(a[0]), "r"(a[1]), "r"(a[2]), "r"(a[3]), "r"(b0), "r"(b1));
}
__device__ __forceinline__ void cp_async16(uint32_t dst, const void* src) {
    asm volatile("cp.async.cg.shared.global [%0], [%1], 16;" :: "r"(dst), "l"(src));
}
__device__ __forceinline__ void cp_commit() {
    asm volatile("cp.async.commit_group;" ::: "memory");
}
__device__ __forceinline__ void cp_wait1() {
    asm volatile("cp.async.wait_group 1;" ::: "memory");
}
__device__ __forceinline__ void cp_wait0() {
    asm volatile("cp.async.wait_group 0;" ::: "memory");
}

// B resident tile: 64 rows x 256 halfs (512 B/row); chunk-XOR swizzle (low 3 bits of chunk)
#define SWZB(r, k) ((r) * 512 + ((((((k) >> 3) & ~7) | ((((k) >> 3) & 7) ^ ((r) & 7)))) << 4))
// A stage: 128 rows x 32 halfs (64 B/row); 4 chunks/row, XOR by (r>>1)&3 (conflict-free for ldsm)
#define SWZA32(r, k) ((r) * 64 + (((((k) >> 3) & 3) ^ (((r) >> 1) & 3)) << 4))

// smem layout (bytes): Bh [0,32K) | Bl [32K,64K) | A ring: 64K + s*16K (hi 8K, lo 8K), s=0..2
#define SM_BL  32768
#define SM_AST 65536
#define SM_TOT (65536 + 3 * 16384)   // 114688 B; 2 CTAs = 224 KB <= 228 KB carveout

// ---------------- pipelined HMMA GEMM, pure cp.async front end, 2 CTAs/SM ----------------
// C[M x 256] = A[M,256] @ Bt[256,256]^T + bias. A pre-split fp16 hi/lo in DRAM.
// 3-term compensated (hh + hl + lh), fp32 acc. Block 128(m) x 64(n); 8 warps (4m x 2n),
// warp tile 32x32. K: 8 chunks of 32, 3-stage cp.async ring, 1 barrier per chunk.
// Dual dispatch: blocks [0,nx0) run problem 0, rest problem 1.
__global__ __launch_bounds__(256, 2)
void hgemm_kernel(const __half* __restrict__ A0h, const __half* __restrict__ A0l,
                  const __half* __restrict__ B0h, const __half* __restrict__ B0l,
                  const float* __restrict__ b0a, const float* __restrict__ b0b,
                  int bsplit0, float* __restrict__ C0, int nx0,
                  const __half* __restrict__ A1h, const __half* __restrict__ A1l,
                  const __half* __restrict__ B1h, const __half* __restrict__ B1l,
                  const float* __restrict__ b1a, const float* __restrict__ b1b,
                  int bsplit1, float* __restrict__ C1)
{
    extern __shared__ char smem[];
    const uint32_t sb = smem_u32(smem);
    const int tid = threadIdx.x;
    const int wid = tid >> 5;
    const int lane = tid & 31;

    const bool p0 = ((int)blockIdx.x < nx0);
    const __half* Ah     = p0 ? A0h : A1h;
    const __half* Al     = p0 ? A0l : A1l;
    const __half* Bh     = p0 ? B0h : B1h;
    const __half* Bl     = p0 ? B0l : B1l;
    const float*  bias0  = p0 ? b0a : b1a;
    const float*  bias1  = p0 ? b0b : b1b;
    const int     bsplit = p0 ? bsplit0 : bsplit1;
    float*        C      = p0 ? C0 : C1;
    const int m0 = (p0 ? blockIdx.x : blockIdx.x - nx0) * 128;
    const int n0 = blockIdx.y * 64;
    const int wm = (wid & 3) * 32;
    const int wn = (wid >> 2) * 32;

    // A chunk issue: 128 rows x 32 halfs (64B/row) per split; 2 x 16B chunks per thread per split
    auto issueA = [&](int kc) {
        const uint32_t st = SM_AST + (kc % 3) * 16384;
#pragma unroll
        for (int i = 0; i < 2; i++) {
            int lin = i * 256 + tid;           // 0..511
            int r = lin >> 2, c = lin & 3;     // row, 16B chunk within 64B row
            uint32_t sw = (uint32_t)(r * 64 + ((c ^ ((r >> 1) & 3)) << 4));
            size_t g = (size_t)(m0 + r) * 256 + kc * 32 + c * 8;
            cp_async16(sb + st + sw,        Ah + g);
            cp_async16(sb + st + 8192 + sw, Al + g);
        }
    };

    // ---- prologue: B (resident) + A chunk 0 in group 1; A chunk 1 in group 2 ----
#pragma unroll
    for (int i = 0; i < 8; i++) {
        int lin = i * 256 + tid;               // 0..2047
        int r = lin >> 5, c = lin & 31;
        size_t g = (size_t)(n0 + r) * 256 + c * 8;
        uint32_t sw = SWZB(r, c * 8);
        cp_async16(sb + sw,         Bh + g);
        cp_async16(sb + SM_BL + sw, Bl + g);
    }
    issueA(0);
    cp_commit();
    issueA(1);
    cp_commit();

    float acc[2][4][4];
#pragma unroll
    for (int i = 0; i < 2; i++)
#pragma unroll
        for (int j = 0; j < 4; j++)
#pragma unroll
            for (int k = 0; k < 4; k++) acc[i][j][k] = 0.f;

    const int a_r  = (lane & 15);
    const int a_k8 = (lane >> 4) << 3;
    const int b_r  = (lane & 7) + ((lane >> 4) << 3);
    const int b_k8 = ((lane >> 3) & 1) << 3;

    for (int kc = 0; kc < 8; ++kc) {
        if (kc == 7) cp_wait0(); else cp_wait1();
        __syncthreads();

        const uint32_t Ahb = sb + SM_AST + (kc % 3) * 16384;
        const uint32_t Alb = Ahb + 8192;
#pragma unroll
        for (int ks = 0; ks < 2; ++ks) {
            const int k0 = ks * 16;
            uint32_t ah[2][4], al[2][4], bh[2][4], bl[2][4];
#pragma unroll
            for (int mi = 0; mi < 2; mi++) {
                int r = wm + mi * 16 + a_r;
                uint32_t sw = SWZA32(r, k0 + a_k8);
                ldmatrix_x4(ah[mi][0], ah[mi][1], ah[mi][2], ah[mi][3], Ahb + sw);
                ldmatrix_x4(al[mi][0], al[mi][1], al[mi][2], al[mi][3], Alb + sw);
            }
#pragma unroll
            for (int np = 0; np < 2; np++) {
                int r = wn + np * 16 + b_r;
                uint32_t sw = SWZB(r, kc * 32 + k0 + b_k8);
                ldmatrix_x4(bh[np][0], bh[np][1], bh[np][2], bh[np][3], sb + sw);
                ldmatrix_x4(bl[np][0], bl[np][1], bl[np][2], bl[np][3], sb + SM_BL + sw);
            }
#pragma unroll
            for (int mi = 0; mi < 2; mi++)
#pragma unroll
                for (int ni = 0; ni < 4; ni++) {
                    uint32_t h0 = bh[ni >> 1][(ni & 1) * 2], h1 = bh[ni >> 1][(ni & 1) * 2 + 1];
                    uint32_t l0 = bl[ni >> 1][(ni & 1) * 2], l1 = bl[ni >> 1][(ni & 1) * 2 + 1];
                    mma16816(acc[mi][ni], ah[mi], h0, h1);   // hh
                    mma16816(acc[mi][ni], ah[mi], l0, l1);   // hl
                    mma16816(acc[mi][ni], al[mi], h0, h1);   // lh
                }
        }

        // issue chunk kc+2 into stage (kc+2)%3 == (kc-1)%3 — its readers (compute kc-1)
        // all passed the barrier at the top of this iteration.
        if (kc < 6) {
            issueA(kc + 2);
            cp_commit();
        }
    }

    // ---- epilogue ----
    const int g  = lane >> 2;
    const int tq = lane & 3;
#pragma unroll
    for (int ni = 0; ni < 4; ni++) {
        int c = n0 + wn + ni * 8 + 2 * tq;
        float bv0 = (c     < bsplit) ? bias0[c]     : bias1[c - bsplit];
        float bv1 = (c + 1 < bsplit) ? bias0[c + 1] : bias1[c + 1 - bsplit];
#pragma unroll
        for (int mi = 0; mi < 2; mi++) {
            int row = m0 + wm + mi * 16 + g;
            *(float2*)(C + (size_t)row * 256 + c)       = make_float2(acc[mi][ni][0] + bv0,
                                                                      acc[mi][ni][1] + bv1);
            *(float2*)(C + (size_t)(row + 8) * 256 + c) = make_float2(acc[mi][ni][2] + bv0,
                                                                      acc[mi][ni][3] + bv1);
        }
    }
}

// ---------------- activation split: fp32 -> fp16 hi/lo, two tensors in one launch ----------------
__global__ void asplit_kernel(const float* __restrict__ a0, __half* __restrict__ h0,
                              __half* __restrict__ l0, int n0_4,
                              const float* __restrict__ a1, __half* __restrict__ h1,
                              __half* __restrict__ l1, int n1_4)
{
    int i = blockIdx.x * blockDim.x + threadIdx.x;
    const float* src;
    __half *hd, *ld;
    if (i < n0_4) { src = a0; hd = h0; ld = l0; }
    else { i -= n0_4; if (i >= n1_4) return; src = a1; hd = h1; ld = l1; }

    float4 v = ((const float4*)src)[i];
    __half h[4], l[4];
    float f[4] = {v.x, v.y, v.z, v.w};
#pragma unroll
    for (int e = 0; e < 4; e++) {
        h[e] = __float2half_rn(f[e]);
        l[e] = __float2half_rn(f[e] - __half2float(h[e]));
    }
    ((uint2*)hd)[i] = *(uint2*)h;
    ((uint2*)ld)[i] = *(uint2*)l;
}

// ---------------- fused weight prep: transpose + fp16 hi/lo split, all 4 matrices ----------------
__global__ void wprep_kernel(const float* __restrict__ W_val, const float* __restrict__ W_off,
                             const float* __restrict__ W_attn, const float* __restrict__ W_out,
                             __half* __restrict__ gwh, __half* __restrict__ gwl)
{
    int idx = blockIdx.x * blockDim.x + threadIdx.x;   // 0 .. 4*65536-1
    int mat = idx >> 16;
    int i   = idx & 65535;
    int n = i >> 8, k = i & 255;

    float x;
    int dst;
    if (mat == 0) {                 // W_val^T -> slot 0
        x = W_val[(size_t)k * 256 + n];
        dst = i;
    } else if (mat == 1) {          // W_off^T -> slot 1 rows [0,128)
        if (n >= 128) return;
        x = W_off[(size_t)k * 128 + n];
        dst = 65536 + n * 256 + k;
    } else if (mat == 2) {          // W_attn^T -> slot 1 rows [128,256)
        if (n >= 128) return;
        x = W_attn[(size_t)k * 128 + n];
        dst = 65536 + (128 + n) * 256 + k;
    } else {                        // W_out^T -> slot 3
        x = W_out[(size_t)k * 256 + n];
        dst = 3 * 65536 + i;
    }
    __half h = __float2half_rn(x);
    gwh[dst] = h;
    gwl[dst] = __float2half_rn(x - __half2float(h));
}

// ---------------- fused loc/softmax + bilinear sampling; emits fp16 hi/lo ----------------
// one warp per (nq, m). lanes 0-15: loc; lanes 16-31: softmaxed attn.
__global__ void sample_kernel(const float* __restrict__ value,
                              const float* __restrict__ goa,
                              const float* __restrict__ refp,
                              float* __restrict__ loc_out,
                              float* __restrict__ attn_out,
                              __half* __restrict__ out_h,
                              __half* __restrict__ out_l)
{
    int warp = (blockIdx.x * blockDim.x + threadIdx.x) >> 5;
    int lane = threadIdx.x & 31;
    if (warp >= NQ * 8) return;
    int m  = warp & 7;
    int nq = warp >> 3;
    int n  = nq >> 11;
    int j  = lane & 15;

    float v = goa[(size_t)nq * 256 + (lane < 16 ? m * 16 + j : 128 + m * 16 + j)];

    // softmax within the upper 16-lane half (lower-half result unused)
    float mx = v;
#pragma unroll
    for (int o = 1; o < 16; o <<= 1) mx = fmaxf(mx, __shfl_xor_sync(0xffffffffu, mx, o));
    float e = __expf(v - mx);
    float s = e;
#pragma unroll
    for (int o = 1; o < 16; o <<= 1) s += __shfl_xor_sync(0xffffffffu, s, o);

    int l4 = j >> 2;
    float myv = (lane < 16) ? (refp[(size_t)nq * 4 + l4] + v * c_invT[l4]) : (e / s);

    if (lane < 16) loc_out[(size_t)warp * 16 + j]  = myv;
    else           attn_out[(size_t)warp * 16 + j] = myv;

    float acc = 0.f;
    const float* vbase = value + (size_t)n * Ssum * 256 + m * 32 + lane;

#pragma unroll
    for (int lp = 0; lp < 16; ++lp) {
        float lv = __shfl_sync(0xffffffffu, myv, lp);        // loc
        float w  = __shfl_sync(0xffffffffu, myv, 16 + lp);   // attn weight
        int l = lp >> 2;
        int T = c_T[l];
        float pos  = lv * (float)T - 0.5f;
        float x0f  = floorf(pos);
        float frac = pos - x0f;
        int x0 = (int)x0f;
        float w0 = (x0 >= 0 && x0 < T) ? (1.f - frac) : 0.f;
        float w1 = (x0 + 1 >= 0 && x0 + 1 < T) ? frac : 0.f;
        if (w0 != 0.f || w1 != 0.f) {
            int i0 = min(max(x0, 0), T - 1);
            int i1 = min(max(x0 + 1, 0), T - 1);
            const float* p = vbase + (size_t)c_S[l] * 256;
            float v0 = p[(size_t)i0 * 256];
            float v1 = p[(size_t)i1 * 256];
            acc += w * (w0 * v0 + w1 * v1);
        }
    }
    __half h = __float2half_rn(acc);
    out_h[(size_t)warp * 32 + lane] = h;
    out_l[(size_t)warp * 32 + lane] = __float2half_rn(acc - __half2float(h));
}

// ---------------- launch ----------------
extern "C" void kernel_launch(void* const* d_in, const int* in_sizes, int n_in,
                              void* d_out, int out_size)
{
    const float* query         = (const float*)d_in[0];
    const float* refpts        = (const float*)d_in[1];
    const float* input_flatten = (const float*)d_in[2];
    const float* W_off  = (const float*)d_in[5];
    const float* b_off  = (const float*)d_in[6];
    const float* W_attn = (const float*)d_in[7];
    const float* b_attn = (const float*)d_in[8];
    const float* W_val  = (const float*)d_in[9];
    const float* b_val  = (const float*)d_in[10];
    const float* W_out  = (const float*)d_in[11];
    const float* b_out  = (const float*)d_in[12];
    float* out = (float*)d_out;

    float *gv, *goa, *gls, *gas;
    __half *gah, *gal, *gqh, *gql, *gth, *gtl, *gwh, *gwl;
    cudaGetSymbolAddress((void**)&gv,  g_value);
    cudaGetSymbolAddress((void**)&goa, g_offattn);
    cudaGetSymbolAddress((void**)&gah, g_ah);
    cudaGetSymbolAddress((void**)&gal, g_al);
    cudaGetSymbolAddress((void**)&gqh, g_qh);
    cudaGetSymbolAddress((void**)&gql, g_ql);
    cudaGetSymbolAddress((void**)&gth, g_th);
    cudaGetSymbolAddress((void**)&gtl, g_tl);
    cudaGetSymbolAddress((void**)&gwh, g_wh);
    cudaGetSymbolAddress((void**)&gwl, g_wl);
    cudaGetSymbolAddress((void**)&gls, g_loc_s);
    cudaGetSymbolAddress((void**)&gas, g_attn_s);

    const int OUT_ELEMS  = NQ * Cc;       // 4194304
    const int LOCA_ELEMS = NQ * 8 * 16;   // 2097152
    float* loc_out  = (out_size >= OUT_ELEMS + 2 * LOCA_ELEMS) ? out + OUT_ELEMS : gls;
    float* attn_out = (out_size >= OUT_ELEMS + 2 * LOCA_ELEMS) ? out + OUT_ELEMS + LOCA_ELEMS : gas;

    cudaFuncSetAttribute(hgemm_kernel, cudaFuncAttributeMaxDynamicSharedMemorySize, SM_TOT);

    __half* wvh = gwh;               __half* wvl = gwl;                // W_val^T
    __half* wqh = gwh + 1 * Cc * Cc; __half* wql = gwl + 1 * Cc * Cc;  // [W_off;W_attn]^T
    __half* woh = gwh + 3 * Cc * Cc; __half* wol = gwl + 3 * Cc * Cc;  // W_out^T

    // 1. weight transpose + split
    wprep_kernel<<<(4 * 65536) / 256, 256>>>(W_val, W_off, W_attn, W_out, gwh, gwl);

    // 2. activation split: input_flatten + query -> fp16 hi/lo
    asplit_kernel<<<(NROWS_VAL * 64 + NQ * 64) / 256, 256>>>(
        input_flatten, gah, gal, NROWS_VAL * 64,
        query,         gqh, gql, NQ * 64);

    // 3. fused: value projection (240 blocks) + off/attn projection (128 blocks), grid.y = 4
    hgemm_kernel<<<dim3(NROWS_VAL / 128 + NQ / 128, 4), 256, SM_TOT>>>(
        gah, gal, wvh, wvl, b_val, b_val, 512, gv, NROWS_VAL / 128,
        gqh, gql, wqh, wql, b_off, b_attn, 128, goa);

    // 4. fused loc/softmax + deformable sampling -> fp16 hi/lo (also outputs loc & attn)
    sample_kernel<<<(NQ * 8) / 8, 256>>>(gv, goa, refpts, loc_out, attn_out, gth, gtl);

    // 5. output projection -> d_out
    hgemm_kernel<<<dim3(NQ / 128, 4), 256, SM_TOT>>>(
        gth, gtl, woh, wol, b_out, b_out, 512, out, NQ / 128,
        gth, gtl, woh, wol, b_out, b_out, 512, out);
}

// round 13
// speedup vs baseline: 1.7653x; 1.7653x over previous
#include <cuda_runtime.h>
#include <cuda_fp16.h>
#include <cstdint>

// ---------------- problem constants ----------------
#define Nb   8
#define LQ   2048
#define Cc   256
#define NQ   (Nb*LQ)        // 16384
#define Ssum 3840
#define NROWS_VAL (Nb*Ssum) // 30720

__device__ __constant__ int   c_T[4]    = {2048, 1024, 512, 256};
__device__ __constant__ int   c_S[4]    = {0, 2048, 3072, 3584};
__device__ __constant__ float c_invT[4] = {1.f/2048.f, 1.f/1024.f, 1.f/512.f, 1.f/256.f};

// ---------------- static scratch ----------------
__device__ float  g_value[NROWS_VAL * Cc];      // fp32 value projection (31.5 MB)
__device__ float  g_offattn[NQ * Cc];           // off logits (0-127) + attn logits (128-255)
__device__ float  g_tmp[NQ * Cc];               // sampled tensor (feeds out-proj)
__device__ __half g_wh[4][Cc * Cc];             // transposed weight hi: 0=val, 1,2=off||attn, 3=out
__device__ __half g_wl[4][Cc * Cc];
__device__ float  g_loc_s[NQ * 8 * 16];
__device__ float  g_attn_s[NQ * 8 * 16];

// ---------------- helpers ----------------
__device__ __forceinline__ uint32_t smem_u32(const void* p) {
    uint32_t a;
    asm("{ .reg .u64 t; cvta.to.shared.u64 t, %1; cvt.u32.u64 %0, t; }" : "=r"(a) : "l"(p));
    return a;
}
__device__ __forceinline__ void ldmatrix_x4(uint32_t& r0, uint32_t& r1, uint32_t& r2, uint32_t& r3,
                                            uint32_t addr) {
    asm volatile("ldmatrix.sync.aligned.m8n8.x4.shared.b16 {%0,%1,%2,%3}, [%4];"
                 : "=r"(r0), "=r"(r1), "=r"(r2), "=r"(r3) : "r"(addr));
}
__device__ __forceinline__ void mma16816(float* c, const uint32_t* a, uint32_t b0, uint32_t b1) {
    asm volatile("mma.sync.aligned.m16n8k16.row.col.f32.f16.f16.f32 "
                 "{%0,%1,%2,%3},{%4,%5,%6,%7},{%8,%9},{%0,%1,%2,%3};"
                 : "+f"(c[0]), "+f"(c[1]), "+f"(c[2]), "+f"(c[3])
                 : "r"(a[0]), "r"(a[1]), "r"(a[2]), "r"(a[3]), "r"(b0), "r"(b1));
}
__device__ __forceinline__ void cp_async16(uint32_t dst, const void* src) {
    asm volatile("cp.async.cg.shared.global [%0], [%1], 16;" :: "r"(dst), "l"(src));
}
__device__ __forceinline__ void cp_async_wait_all() {
    asm volatile("cp.async.commit_group;\n\tcp.async.wait_group 0;" ::: "memory");
}

// B resident tile: 64 rows x 256 halfs (512 B/row); chunk-XOR swizzle (low 3 bits of chunk)
#define SWZB(r, k) ((r) * 512 + ((((((k) >> 3) & ~7) | ((((k) >> 3) & 7) ^ ((r) & 7)))) << 4))
// A stage: 128 rows x 32 halfs (64 B/row); 4 chunks/row, XOR by (r>>1)&3 (conflict-free for ldsm)
#define SWZA32(r, k) ((r) * 64 + (((((k) >> 3) & 3) ^ (((r) >> 1) & 3)) << 4))

// smem layout (bytes): Bh [0,32K) | Bl [32K,64K) | A stages: 64K + s*16K (Ah 8K, Al 8K)
#define SM_BL  32768
#define SM_AST 65536
#define SM_TOT 98304

// ---------------- pipelined HMMA GEMM, 2 CTAs/SM, fused fp32->fp16 hi/lo split of A ----------
// C[M x 256] = A[M,256] @ Bt[256,256]^T + bias.  3-term compensated (hh + hl + lh), fp32 acc.
// Block 128(m) x 64(n); 8 warps = 4m x 2n, warp tile 32x32. K: 8 pipelined chunks of 32.
// Dual dispatch: blocks [0,nx0) run problem 0, rest run problem 1.
__global__ __launch_bounds__(256, 2)
void hgemm_kernel(const float* __restrict__ A0, const __half* __restrict__ B0h,
                  const __half* __restrict__ B0l, const float* __restrict__ b0a,
                  const float* __restrict__ b0b, int bsplit0, float* __restrict__ C0, int nx0,
                  const float* __restrict__ A1, const __half* __restrict__ B1h,
                  const __half* __restrict__ B1l, const float* __restrict__ b1a,
                  const float* __restrict__ b1b, int bsplit1, float* __restrict__ C1)
{
    extern __shared__ char smem[];
    const uint32_t sb = smem_u32(smem);
    const int tid = threadIdx.x;
    const int wid = tid >> 5;
    const int lane = tid & 31;

    const bool p0 = ((int)blockIdx.x < nx0);
    const float*  A      = p0 ? A0 : A1;
    const __half* Bh     = p0 ? B0h : B1h;
    const __half* Bl     = p0 ? B0l : B1l;
    const float*  bias0  = p0 ? b0a : b1a;
    const float*  bias1  = p0 ? b0b : b1b;
    const int     bsplit = p0 ? bsplit0 : bsplit1;
    float*        C      = p0 ? C0 : C1;
    const int m0 = (p0 ? blockIdx.x : blockIdx.x - nx0) * 128;
    const int n0 = blockIdx.y * 64;
    const int wm = (wid & 3) * 32;
    const int wn = (wid >> 2) * 32;

    // ---- B resident load (once): 64 rows x 256 k, hi+lo, via cp.async ----
#pragma unroll
    for (int i = 0; i < 8; i++) {
        int lin = i * 256 + tid;                 // 0..2047
        int r = lin >> 5, c = lin & 31;          // row, 16B-chunk
        size_t g = (size_t)(n0 + r) * 256 + c * 8;
        uint32_t sw = SWZB(r, c * 8);
        cp_async16(sb + sw,         Bh + g);
        cp_async16(sb + SM_BL + sw, Bl + g);
    }

    // ---- A loader mapping: thread t -> row tid>>1, 16-half half (tid&1) of the 32-wide chunk ----
    const int a_r0   = tid >> 1;
    const int a_half = tid & 1;
    const float* Abase = A + (size_t)(m0 + a_r0) * 256 + a_half * 16;

    float4 pre[4];
#pragma unroll
    for (int i = 0; i < 4; i++) pre[i] = *(const float4*)(Abase + i * 4);

    // convert chunk 0 -> stage 0
    {
        float f[16] = {pre[0].x, pre[0].y, pre[0].z, pre[0].w, pre[1].x, pre[1].y, pre[1].z, pre[1].w,
                       pre[2].x, pre[2].y, pre[2].z, pre[2].w, pre[3].x, pre[3].y, pre[3].z, pre[3].w};
        __half h[16], l[16];
#pragma unroll
        for (int e = 0; e < 16; e++) {
            h[e] = __float2half_rn(f[e]);
            l[e] = __float2half_rn(f[e] - __half2float(h[e]));
        }
#pragma unroll
        for (int j = 0; j < 2; j++) {
            uint32_t sw = (uint32_t)(a_r0 * 64 + (((a_half * 2 + j) ^ ((a_r0 >> 1) & 3)) << 4));
            *(uint4*)(smem + SM_AST + sw)        = ((uint4*)h)[j];
            *(uint4*)(smem + SM_AST + 8192 + sw) = ((uint4*)l)[j];
        }
    }
    cp_async_wait_all();
    __syncthreads();

    float acc[2][4][4];
#pragma unroll
    for (int i = 0; i < 2; i++)
#pragma unroll
        for (int j = 0; j < 4; j++)
#pragma unroll
            for (int k = 0; k < 4; k++) acc[i][j][k] = 0.f;

    const int a_r  = (lane & 15);
    const int a_k8 = (lane >> 4) << 3;
    const int b_r  = (lane & 7) + ((lane >> 4) << 3);
    const int b_k8 = ((lane >> 3) & 1) << 3;

    for (int kc = 0; kc < 8; ++kc) {
        // prefetch next A chunk (hidden under MMAs below)
        if (kc < 7) {
#pragma unroll
            for (int i = 0; i < 4; i++)
                pre[i] = *(const float4*)(Abase + (kc + 1) * 32 + i * 4);
        }

        const uint32_t Ahb = sb + SM_AST + (kc & 1) * 16384;
        const uint32_t Alb = Ahb + 8192;
#pragma unroll
        for (int ks = 0; ks < 2; ++ks) {
            const int k0 = ks * 16;
            uint32_t ah[2][4], al[2][4], bh[2][4], bl[2][4];
#pragma unroll
            for (int mi = 0; mi < 2; mi++) {
                int r = wm + mi * 16 + a_r;
                uint32_t sw = SWZA32(r, k0 + a_k8);
                ldmatrix_x4(ah[mi][0], ah[mi][1], ah[mi][2], ah[mi][3], Ahb + sw);
                ldmatrix_x4(al[mi][0], al[mi][1], al[mi][2], al[mi][3], Alb + sw);
            }
#pragma unroll
            for (int np = 0; np < 2; np++) {
                int r = wn + np * 16 + b_r;
                uint32_t sw = SWZB(r, kc * 32 + k0 + b_k8);
                ldmatrix_x4(bh[np][0], bh[np][1], bh[np][2], bh[np][3], sb + sw);
                ldmatrix_x4(bl[np][0], bl[np][1], bl[np][2], bl[np][3], sb + SM_BL + sw);
            }
#pragma unroll
            for (int mi = 0; mi < 2; mi++)
#pragma unroll
                for (int ni = 0; ni < 4; ni++) {
                    uint32_t h0 = bh[ni >> 1][(ni & 1) * 2], h1 = bh[ni >> 1][(ni & 1) * 2 + 1];
                    uint32_t l0 = bl[ni >> 1][(ni & 1) * 2], l1 = bl[ni >> 1][(ni & 1) * 2 + 1];
                    mma16816(acc[mi][ni], ah[mi], h0, h1);   // hh
                    mma16816(acc[mi][ni], ah[mi], l0, l1);   // hl
                    mma16816(acc[mi][ni], al[mi], h0, h1);   // lh
                }
        }

        // convert prefetched chunk -> other stage (safe: other stage idle since last sync)
        if (kc < 7) {
            uint32_t dst = SM_AST + ((kc + 1) & 1) * 16384;
            float f[16] = {pre[0].x, pre[0].y, pre[0].z, pre[0].w, pre[1].x, pre[1].y, pre[1].z, pre[1].w,
                           pre[2].x, pre[2].y, pre[2].z, pre[2].w, pre[3].x, pre[3].y, pre[3].z, pre[3].w};
            __half h[16], l[16];
#pragma unroll
            for (int e = 0; e < 16; e++) {
                h[e] = __float2half_rn(f[e]);
                l[e] = __float2half_rn(f[e] - __half2float(h[e]));
            }
#pragma unroll
            for (int j = 0; j < 2; j++) {
                uint32_t sw = (uint32_t)(a_r0 * 64 + (((a_half * 2 + j) ^ ((a_r0 >> 1) & 3)) << 4));
                *(uint4*)(smem + dst + sw)        = ((uint4*)h)[j];
                *(uint4*)(smem + dst + 8192 + sw) = ((uint4*)l)[j];
            }
        }
        __syncthreads();
    }

    // ---- epilogue ----
    const int g  = lane >> 2;
    const int tq = lane & 3;
#pragma unroll
    for (int ni = 0; ni < 4; ni++) {
        int c = n0 + wn + ni * 8 + 2 * tq;
        float bv0 = (c     < bsplit) ? bias0[c]     : bias1[c - bsplit];
        float bv1 = (c + 1 < bsplit) ? bias0[c + 1] : bias1[c + 1 - bsplit];
#pragma unroll
        for (int mi = 0; mi < 2; mi++) {
            int row = m0 + wm + mi * 16 + g;
            *(float2*)(C + (size_t)row * 256 + c)       = make_float2(acc[mi][ni][0] + bv0,
                                                                      acc[mi][ni][1] + bv1);
            *(float2*)(C + (size_t)(row + 8) * 256 + c) = make_float2(acc[mi][ni][2] + bv0,
                                                                      acc[mi][ni][3] + bv1);
        }
    }
}

// ---------------- fused weight prep: transpose + fp16 hi/lo split, all 4 matrices ----------------
__global__ void wprep_kernel(const float* __restrict__ W_val, const float* __restrict__ W_off,
                             const float* __restrict__ W_attn, const float* __restrict__ W_out,
                             __half* __restrict__ gwh, __half* __restrict__ gwl)
{
    int idx = blockIdx.x * blockDim.x + threadIdx.x;   // 0 .. 4*65536-1
    int mat = idx >> 16;
    int i   = idx & 65535;
    int n = i >> 8, k = i & 255;

    float x;
    int dst;
    if (mat == 0) {                 // W_val^T -> slot 0
        x = W_val[(size_t)k * 256 + n];
        dst = i;
    } else if (mat == 1) {          // W_off^T -> slot 1 rows [0,128)
        if (n >= 128) return;
        x = W_off[(size_t)k * 128 + n];
        dst = 65536 + n * 256 + k;
    } else if (mat == 2) {          // W_attn^T -> slot 1 rows [128,256)
        if (n >= 128) return;
        x = W_attn[(size_t)k * 128 + n];
        dst = 65536 + (128 + n) * 256 + k;
    } else {                        // W_out^T -> slot 3
        x = W_out[(size_t)k * 256 + n];
        dst = 3 * 65536 + i;
    }
    __half h = __float2half_rn(x);
    gwh[dst] = h;
    gwl[dst] = __float2half_rn(x - __half2float(h));
}

// ---------------- fused loc/softmax + bilinear sampling (issue-optimized inner loop) ----------
// one warp per (nq, m). lanes 0-15: loc; lanes 16-31: softmaxed attn.
// Per-point offsets & attn-premultiplied weights are precomputed in lanes 0-15;
// the 16-point loop is 4 shfl + 2 LDG + 2 FMA per iteration.
__global__ void sample_kernel(const float* __restrict__ value,
                              const float* __restrict__ goa,
                              const float* __restrict__ refp,
                              float* __restrict__ loc_out,
                              float* __restrict__ attn_out,
                              float* __restrict__ outv)
{
    int warp = (blockIdx.x * blockDim.x + threadIdx.x) >> 5;
    int lane = threadIdx.x & 31;
    if (warp >= NQ * 8) return;
    int m  = warp & 7;
    int nq = warp >> 3;
    int n  = nq >> 11;
    int j  = lane & 15;

    float v = goa[(size_t)nq * 256 + (lane < 16 ? m * 16 + j : 128 + m * 16 + j)];

    // softmax within the upper 16-lane half (lower-half result unused)
    float mx = v;
#pragma unroll
    for (int o = 1; o < 16; o <<= 1) mx = fmaxf(mx, __shfl_xor_sync(0xffffffffu, mx, o));
    float e = __expf(v - mx);
    float s = e;
#pragma unroll
    for (int o = 1; o < 16; o <<= 1) s += __shfl_xor_sync(0xffffffffu, s, o);

    int l4 = j >> 2;
    float myv = (lane < 16) ? (refp[(size_t)nq * 4 + l4] + v * c_invT[l4]) : (e / s);

    if (lane < 16) loc_out[(size_t)warp * 16 + j]  = myv;
    else           attn_out[(size_t)warp * 16 + j] = myv;

    // ---- precompute per-point data (meaningful in lanes 0-15; shuffles read only lp<16) ----
    float aw = __shfl_sync(0xffffffffu, myv, 16 + j);   // attn weight of point j
    int   T = c_T[l4], S = c_S[l4];
    float pos  = myv * (float)T - 0.5f;                 // myv = loc in lanes 0-15
    float x0f  = floorf(pos);
    float frac = pos - x0f;
    int   x0   = (int)x0f;
    float fw0 = ((x0 >= 0 && x0 < T) ? (1.f - frac) : 0.f) * aw;
    float fw1 = ((x0 + 1 >= 0 && x0 + 1 < T) ? frac : 0.f) * aw;
    int ofs0 = (S + min(max(x0, 0), T - 1)) * 256;      // element offsets (fit in int)
    int ofs1 = (S + min(max(x0 + 1, 0), T - 1)) * 256;

    const float* vbase = value + (size_t)n * Ssum * 256 + m * 32 + lane;
    float acc = 0.f;
#pragma unroll
    for (int lp = 0; lp < 16; ++lp) {
        int   o0 = __shfl_sync(0xffffffffu, ofs0, lp);
        int   o1 = __shfl_sync(0xffffffffu, ofs1, lp);
        float w0 = __shfl_sync(0xffffffffu, fw0, lp);
        float w1 = __shfl_sync(0xffffffffu, fw1, lp);
        acc += w0 * __ldg(vbase + o0) + w1 * __ldg(vbase + o1);
    }
    outv[(size_t)warp * 32 + lane] = acc;
}

// ---------------- launch ----------------
extern "C" void kernel_launch(void* const* d_in, const int* in_sizes, int n_in,
                              void* d_out, int out_size)
{
    const float* query         = (const float*)d_in[0];
    const float* refpts        = (const float*)d_in[1];
    const float* input_flatten = (const float*)d_in[2];
    const float* W_off  = (const float*)d_in[5];
    const float* b_off  = (const float*)d_in[6];
    const float* W_attn = (const float*)d_in[7];
    const float* b_attn = (const float*)d_in[8];
    const float* W_val  = (const float*)d_in[9];
    const float* b_val  = (const float*)d_in[10];
    const float* W_out  = (const float*)d_in[11];
    const float* b_out  = (const float*)d_in[12];
    float* out = (float*)d_out;

    float *gv, *goa, *gt, *gls, *gas;
    __half *gwh, *gwl;
    cudaGetSymbolAddress((void**)&gv,  g_value);
    cudaGetSymbolAddress((void**)&goa, g_offattn);
    cudaGetSymbolAddress((void**)&gt,  g_tmp);
    cudaGetSymbolAddress((void**)&gwh, g_wh);
    cudaGetSymbolAddress((void**)&gwl, g_wl);
    cudaGetSymbolAddress((void**)&gls, g_loc_s);
    cudaGetSymbolAddress((void**)&gas, g_attn_s);

    const int OUT_ELEMS  = NQ * Cc;       // 4194304
    const int LOCA_ELEMS = NQ * 8 * 16;   // 2097152
    float* loc_out  = (out_size >= OUT_ELEMS + 2 * LOCA_ELEMS) ? out + OUT_ELEMS : gls;
    float* attn_out = (out_size >= OUT_ELEMS + 2 * LOCA_ELEMS) ? out + OUT_ELEMS + LOCA_ELEMS : gas;

    cudaFuncSetAttribute(hgemm_kernel, cudaFuncAttributeMaxDynamicSharedMemorySize, SM_TOT);

    __half* wvh = gwh;               __half* wvl = gwl;                // W_val^T
    __half* wqh = gwh + 1 * Cc * Cc; __half* wql = gwl + 1 * Cc * Cc;  // [W_off;W_attn]^T
    __half* woh = gwh + 3 * Cc * Cc; __half* wol = gwl + 3 * Cc * Cc;  // W_out^T

    // 1. weight transpose + split (one launch)
    wprep_kernel<<<(4 * 65536) / 256, 256>>>(W_val, W_off, W_attn, W_out, gwh, gwl);

    // 2. fused: value projection (240 blocks) + off/attn projection (128 blocks), grid.y = 4
    hgemm_kernel<<<dim3(NROWS_VAL / 128 + NQ / 128, 4), 256, SM_TOT>>>(
        input_flatten, wvh, wvl, b_val, b_val, 512, gv, NROWS_VAL / 128,
        query,         wqh, wql, b_off, b_attn, 128, goa);

    // 3. fused loc/softmax + deformable sampling -> fp32 tmp (also outputs loc & attn)
    sample_kernel<<<(NQ * 8) / 8, 256>>>(gv, goa, refpts, loc_out, attn_out, gt);

    // 4. output projection -> d_out
    hgemm_kernel<<<dim3(NQ / 128, 4), 256, SM_TOT>>>(
        gt, woh, wol, b_out, b_out, 512, out, NQ / 128,
        gt, woh, wol, b_out, b_out, 512, out);
}

// round 14
// speedup vs baseline: 1.9067x; 1.0801x over previous
#include <cuda_runtime.h>
#include <cuda_fp16.h>
#include <cstdint>

// ---------------- problem constants ----------------
#define Nb   8
#define LQ   2048
#define Cc   256
#define NQ   (Nb*LQ)        // 16384
#define Ssum 3840
#define NROWS_VAL (Nb*Ssum) // 30720

__device__ __constant__ int   c_T[4]    = {2048, 1024, 512, 256};
__device__ __constant__ int   c_S[4]    = {0, 2048, 3072, 3584};
__device__ __constant__ float c_invT[4] = {1.f/2048.f, 1.f/1024.f, 1.f/512.f, 1.f/256.f};

// ---------------- static scratch ----------------
__device__ float  g_value[NROWS_VAL * Cc];      // fp32 value projection (31.5 MB)
__device__ float  g_offattn[NQ * Cc];           // off logits (0-127) + attn logits (128-255)
__device__ float  g_tmp[NQ * Cc];               // sampled tensor (feeds out-proj)
__device__ __half g_wh[4][Cc * Cc];             // transposed weight hi: 0=val, 1,2=off||attn, 3=out
__device__ __half g_wl[4][Cc * Cc];
__device__ float  g_loc_s[NQ * 8 * 16];
__device__ float  g_attn_s[NQ * 8 * 16];

// ---------------- helpers ----------------
__device__ __forceinline__ uint32_t smem_u32(const void* p) {
    uint32_t a;
    asm("{ .reg .u64 t; cvta.to.shared.u64 t, %1; cvt.u32.u64 %0, t; }" : "=r"(a) : "l"(p));
    return a;
}
__device__ __forceinline__ void ldmatrix_x4(uint32_t& r0, uint32_t& r1, uint32_t& r2, uint32_t& r3,
                                            uint32_t addr) {
    asm volatile("ldmatrix.sync.aligned.m8n8.x4.shared.b16 {%0,%1,%2,%3}, [%4];"
                 : "=r"(r0), "=r"(r1), "=r"(r2), "=r"(r3) : "r"(addr));
}
__device__ __forceinline__ void mma16816(float* c, const uint32_t* a, uint32_t b0, uint32_t b1) {
    asm volatile("mma.sync.aligned.m16n8k16.row.col.f32.f16.f16.f32 "
                 "{%0,%1,%2,%3},{%4,%5,%6,%7},{%8,%9},{%0,%1,%2,%3};"
                 : "+f"(c[0]), "+f"(c[1]), "+f"(c[2]), "+f"(c[3])
                 : "r"(a[0]), "r"(a[1]), "r"(a[2]), "r"(a[3]), "r"(b0), "r"(b1));
}
__device__ __forceinline__ void cp_async16(uint32_t dst, const void* src) {
    asm volatile("cp.async.cg.shared.global [%0], [%1], 16;" :: "r"(dst), "l"(src));
}
__device__ __forceinline__ void cp_async_wait_all() {
    asm volatile("cp.async.commit_group;\n\tcp.async.wait_group 0;" ::: "memory");
}

// B resident tile: 64 rows x 256 halfs (512 B/row); chunk-XOR swizzle (low 3 bits of chunk)
#define SWZB(r, k) ((r) * 512 + ((((((k) >> 3) & ~7) | ((((k) >> 3) & 7) ^ ((r) & 7)))) << 4))
// A stage: 128 rows x 32 halfs (64 B/row); 4 chunks/row, XOR by (r>>1)&3 (conflict-free for ldsm)
#define SWZA32(r, k) ((r) * 64 + (((((k) >> 3) & 3) ^ (((r) >> 1) & 3)) << 4))

// smem layout (bytes): Bh [0,32K) | Bl [32K,64K) | A hi stages: 64K + s*8K
#define SM_BL  32768
#define SM_AST 65536
#define SM_TOT 81920

// ---------------- pipelined HMMA GEMM, 2 CTAs/SM, fused fp32->fp16 split of A (hi only) ------
// C[M x 256] = A[M,256] @ Bt[256,256]^T + bias.  2-term: D = Ah*(Bh+Bl) = Ah*B (fp32 acc);
// residual error = Al*B ~ 1.4e-4 RMS (activation fp16 rounding), well under the 1e-3 gate.
// Block 128(m) x 64(n); 8 warps = 4m x 2n, warp tile 32x32. K: 8 pipelined chunks of 32.
// Dual dispatch: blocks [0,nx0) run problem 0, rest run problem 1.
__global__ __launch_bounds__(256, 2)
void hgemm_kernel(const float* __restrict__ A0, const __half* __restrict__ B0h,
                  const __half* __restrict__ B0l, const float* __restrict__ b0a,
                  const float* __restrict__ b0b, int bsplit0, float* __restrict__ C0, int nx0,
                  const float* __restrict__ A1, const __half* __restrict__ B1h,
                  const __half* __restrict__ B1l, const float* __restrict__ b1a,
                  const float* __restrict__ b1b, int bsplit1, float* __restrict__ C1)
{
    extern __shared__ char smem[];
    const uint32_t sb = smem_u32(smem);
    const int tid = threadIdx.x;
    const int wid = tid >> 5;
    const int lane = tid & 31;

    const bool p0 = ((int)blockIdx.x < nx0);
    const float*  A      = p0 ? A0 : A1;
    const __half* Bh     = p0 ? B0h : B1h;
    const __half* Bl     = p0 ? B0l : B1l;
    const float*  bias0  = p0 ? b0a : b1a;
    const float*  bias1  = p0 ? b0b : b1b;
    const int     bsplit = p0 ? bsplit0 : bsplit1;
    float*        C      = p0 ? C0 : C1;
    const int m0 = (p0 ? blockIdx.x : blockIdx.x - nx0) * 128;
    const int n0 = blockIdx.y * 64;
    const int wm = (wid & 3) * 32;
    const int wn = (wid >> 2) * 32;

    // ---- B resident load (once): 64 rows x 256 k, hi+lo, via cp.async ----
#pragma unroll
    for (int i = 0; i < 8; i++) {
        int lin = i * 256 + tid;                 // 0..2047
        int r = lin >> 5, c = lin & 31;          // row, 16B-chunk
        size_t g = (size_t)(n0 + r) * 256 + c * 8;
        uint32_t sw = SWZB(r, c * 8);
        cp_async16(sb + sw,         Bh + g);
        cp_async16(sb + SM_BL + sw, Bl + g);
    }

    // ---- A loader mapping: thread t -> row tid>>1, 16-half half (tid&1) of the 32-wide chunk ----
    const int a_r0   = tid >> 1;
    const int a_half = tid & 1;
    const float* Abase = A + (size_t)(m0 + a_r0) * 256 + a_half * 16;

    float4 pre[4];
#pragma unroll
    for (int i = 0; i < 4; i++) pre[i] = *(const float4*)(Abase + i * 4);

    // convert chunk 0 (hi only) -> stage 0
    {
        float f[16] = {pre[0].x, pre[0].y, pre[0].z, pre[0].w, pre[1].x, pre[1].y, pre[1].z, pre[1].w,
                       pre[2].x, pre[2].y, pre[2].z, pre[2].w, pre[3].x, pre[3].y, pre[3].z, pre[3].w};
        __half h[16];
#pragma unroll
        for (int e = 0; e < 16; e++) h[e] = __float2half_rn(f[e]);
#pragma unroll
        for (int j = 0; j < 2; j++) {
            uint32_t sw = (uint32_t)(a_r0 * 64 + (((a_half * 2 + j) ^ ((a_r0 >> 1) & 3)) << 4));
            *(uint4*)(smem + SM_AST + sw) = ((uint4*)h)[j];
        }
    }
    cp_async_wait_all();
    __syncthreads();

    float acc[2][4][4];
#pragma unroll
    for (int i = 0; i < 2; i++)
#pragma unroll
        for (int j = 0; j < 4; j++)
#pragma unroll
            for (int k = 0; k < 4; k++) acc[i][j][k] = 0.f;

    const int a_r  = (lane & 15);
    const int a_k8 = (lane >> 4) << 3;
    const int b_r  = (lane & 7) + ((lane >> 4) << 3);
    const int b_k8 = ((lane >> 3) & 1) << 3;

    for (int kc = 0; kc < 8; ++kc) {
        // prefetch next A chunk (hidden under MMAs below)
        if (kc < 7) {
#pragma unroll
            for (int i = 0; i < 4; i++)
                pre[i] = *(const float4*)(Abase + (kc + 1) * 32 + i * 4);
        }

        const uint32_t Ahb = sb + SM_AST + (kc & 1) * 8192;
#pragma unroll
        for (int ks = 0; ks < 2; ++ks) {
            const int k0 = ks * 16;
            uint32_t ah[2][4], bh[2][4], bl[2][4];
#pragma unroll
            for (int mi = 0; mi < 2; mi++) {
                int r = wm + mi * 16 + a_r;
                ldmatrix_x4(ah[mi][0], ah[mi][1], ah[mi][2], ah[mi][3],
                            Ahb + SWZA32(r, k0 + a_k8));
            }
#pragma unroll
            for (int np = 0; np < 2; np++) {
                int r = wn + np * 16 + b_r;
                uint32_t sw = SWZB(r, kc * 32 + k0 + b_k8);
                ldmatrix_x4(bh[np][0], bh[np][1], bh[np][2], bh[np][3], sb + sw);
                ldmatrix_x4(bl[np][0], bl[np][1], bl[np][2], bl[np][3], sb + SM_BL + sw);
            }
#pragma unroll
            for (int mi = 0; mi < 2; mi++)
#pragma unroll
                for (int ni = 0; ni < 4; ni++) {
                    uint32_t h0 = bh[ni >> 1][(ni & 1) * 2], h1 = bh[ni >> 1][(ni & 1) * 2 + 1];
                    uint32_t l0 = bl[ni >> 1][(ni & 1) * 2], l1 = bl[ni >> 1][(ni & 1) * 2 + 1];
                    mma16816(acc[mi][ni], ah[mi], h0, h1);   // Ah * Bh
                    mma16816(acc[mi][ni], ah[mi], l0, l1);   // Ah * Bl
                }
        }

        // convert prefetched chunk (hi only) -> other stage
        if (kc < 7) {
            uint32_t dst = SM_AST + ((kc + 1) & 1) * 8192;
            float f[16] = {pre[0].x, pre[0].y, pre[0].z, pre[0].w, pre[1].x, pre[1].y, pre[1].z, pre[1].w,
                           pre[2].x, pre[2].y, pre[2].z, pre[2].w, pre[3].x, pre[3].y, pre[3].z, pre[3].w};
            __half h[16];
#pragma unroll
            for (int e = 0; e < 16; e++) h[e] = __float2half_rn(f[e]);
#pragma unroll
            for (int j = 0; j < 2; j++) {
                uint32_t sw = (uint32_t)(a_r0 * 64 + (((a_half * 2 + j) ^ ((a_r0 >> 1) & 3)) << 4));
                *(uint4*)(smem + dst + sw) = ((uint4*)h)[j];
            }
        }
        __syncthreads();
    }

    // ---- epilogue ----
    const int g  = lane >> 2;
    const int tq = lane & 3;
#pragma unroll
    for (int ni = 0; ni < 4; ni++) {
        int c = n0 + wn + ni * 8 + 2 * tq;
        float bv0 = (c     < bsplit) ? bias0[c]     : bias1[c - bsplit];
        float bv1 = (c + 1 < bsplit) ? bias0[c + 1] : bias1[c + 1 - bsplit];
#pragma unroll
        for (int mi = 0; mi < 2; mi++) {
            int row = m0 + wm + mi * 16 + g;
            *(float2*)(C + (size_t)row * 256 + c)       = make_float2(acc[mi][ni][0] + bv0,
                                                                      acc[mi][ni][1] + bv1);
            *(float2*)(C + (size_t)(row + 8) * 256 + c) = make_float2(acc[mi][ni][2] + bv0,
                                                                      acc[mi][ni][3] + bv1);
        }
    }
}

// ---------------- fused weight prep: transpose + fp16 hi/lo split, all 4 matrices ----------------
__global__ void wprep_kernel(const float* __restrict__ W_val, const float* __restrict__ W_off,
                             const float* __restrict__ W_attn, const float* __restrict__ W_out,
                             __half* __restrict__ gwh, __half* __restrict__ gwl)
{
    int idx = blockIdx.x * blockDim.x + threadIdx.x;   // 0 .. 4*65536-1
    int mat = idx >> 16;
    int i   = idx & 65535;
    int n = i >> 8, k = i & 255;

    float x;
    int dst;
    if (mat == 0) {                 // W_val^T -> slot 0
        x = W_val[(size_t)k * 256 + n];
        dst = i;
    } else if (mat == 1) {          // W_off^T -> slot 1 rows [0,128)
        if (n >= 128) return;
        x = W_off[(size_t)k * 128 + n];
        dst = 65536 + n * 256 + k;
    } else if (mat == 2) {          // W_attn^T -> slot 1 rows [128,256)
        if (n >= 128) return;
        x = W_attn[(size_t)k * 128 + n];
        dst = 65536 + (128 + n) * 256 + k;
    } else {                        // W_out^T -> slot 3
        x = W_out[(size_t)k * 256 + n];
        dst = 3 * 65536 + i;
    }
    __half h = __float2half_rn(x);
    gwh[dst] = h;
    gwl[dst] = __float2half_rn(x - __half2float(h));
}

// ---------------- fused loc/softmax + bilinear sampling (issue-optimized inner loop) ----------
// one warp per (nq, m). lanes 0-15: loc; lanes 16-31: softmaxed attn.
// Per-point offsets & attn-premultiplied weights are precomputed in lanes 0-15;
// the 16-point loop is 4 shfl + 2 LDG + 2 FMA per iteration.
__global__ void sample_kernel(const float* __restrict__ value,
                              const float* __restrict__ goa,
                              const float* __restrict__ refp,
                              float* __restrict__ loc_out,
                              float* __restrict__ attn_out,
                              float* __restrict__ outv)
{
    int warp = (blockIdx.x * blockDim.x + threadIdx.x) >> 5;
    int lane = threadIdx.x & 31;
    if (warp >= NQ * 8) return;
    int m  = warp & 7;
    int nq = warp >> 3;
    int n  = nq >> 11;
    int j  = lane & 15;

    float v = goa[(size_t)nq * 256 + (lane < 16 ? m * 16 + j : 128 + m * 16 + j)];

    // softmax within the upper 16-lane half (lower-half result unused)
    float mx = v;
#pragma unroll
    for (int o = 1; o < 16; o <<= 1) mx = fmaxf(mx, __shfl_xor_sync(0xffffffffu, mx, o));
    float e = __expf(v - mx);
    float s = e;
#pragma unroll
    for (int o = 1; o < 16; o <<= 1) s += __shfl_xor_sync(0xffffffffu, s, o);

    int l4 = j >> 2;
    float myv = (lane < 16) ? (refp[(size_t)nq * 4 + l4] + v * c_invT[l4]) : (e / s);

    if (lane < 16) loc_out[(size_t)warp * 16 + j]  = myv;
    else           attn_out[(size_t)warp * 16 + j] = myv;

    // ---- precompute per-point data (meaningful in lanes 0-15; shuffles read only lp<16) ----
    float aw = __shfl_sync(0xffffffffu, myv, 16 + j);   // attn weight of point j
    int   T = c_T[l4], S = c_S[l4];
    float pos  = myv * (float)T - 0.5f;                 // myv = loc in lanes 0-15
    float x0f  = floorf(pos);
    float frac = pos - x0f;
    int   x0   = (int)x0f;
    float fw0 = ((x0 >= 0 && x0 < T) ? (1.f - frac) : 0.f) * aw;
    float fw1 = ((x0 + 1 >= 0 && x0 + 1 < T) ? frac : 0.f) * aw;
    int ofs0 = (S + min(max(x0, 0), T - 1)) * 256;      // element offsets (fit in int)
    int ofs1 = (S + min(max(x0 + 1, 0), T - 1)) * 256;

    const float* vbase = value + (size_t)n * Ssum * 256 + m * 32 + lane;
    float acc = 0.f;
#pragma unroll
    for (int lp = 0; lp < 16; ++lp) {
        int   o0 = __shfl_sync(0xffffffffu, ofs0, lp);
        int   o1 = __shfl_sync(0xffffffffu, ofs1, lp);
        float w0 = __shfl_sync(0xffffffffu, fw0, lp);
        float w1 = __shfl_sync(0xffffffffu, fw1, lp);
        acc += w0 * __ldg(vbase + o0) + w1 * __ldg(vbase + o1);
    }
    outv[(size_t)warp * 32 + lane] = acc;
}

// ---------------- launch ----------------
extern "C" void kernel_launch(void* const* d_in, const int* in_sizes, int n_in,
                              void* d_out, int out_size)
{
    const float* query         = (const float*)d_in[0];
    const float* refpts        = (const float*)d_in[1];
    const float* input_flatten = (const float*)d_in[2];
    const float* W_off  = (const float*)d_in[5];
    const float* b_off  = (const float*)d_in[6];
    const float* W_attn = (const float*)d_in[7];
    const float* b_attn = (const float*)d_in[8];
    const float* W_val  = (const float*)d_in[9];
    const float* b_val  = (const float*)d_in[10];
    const float* W_out  = (const float*)d_in[11];
    const float* b_out  = (const float*)d_in[12];
    float* out = (float*)d_out;

    float *gv, *goa, *gt, *gls, *gas;
    __half *gwh, *gwl;
    cudaGetSymbolAddress((void**)&gv,  g_value);
    cudaGetSymbolAddress((void**)&goa, g_offattn);
    cudaGetSymbolAddress((void**)&gt,  g_tmp);
    cudaGetSymbolAddress((void**)&gwh, g_wh);
    cudaGetSymbolAddress((void**)&gwl, g_wl);
    cudaGetSymbolAddress((void**)&gls, g_loc_s);
    cudaGetSymbolAddress((void**)&gas, g_attn_s);

    const int OUT_ELEMS  = NQ * Cc;       // 4194304
    const int LOCA_ELEMS = NQ * 8 * 16;   // 2097152
    float* loc_out  = (out_size >= OUT_ELEMS + 2 * LOCA_ELEMS) ? out + OUT_ELEMS : gls;
    float* attn_out = (out_size >= OUT_ELEMS + 2 * LOCA_ELEMS) ? out + OUT_ELEMS + LOCA_ELEMS : gas;

    cudaFuncSetAttribute(hgemm_kernel, cudaFuncAttributeMaxDynamicSharedMemorySize, SM_TOT);

    __half* wvh = gwh;               __half* wvl = gwl;                // W_val^T
    __half* wqh = gwh + 1 * Cc * Cc; __half* wql = gwl + 1 * Cc * Cc;  // [W_off;W_attn]^T
    __half* woh = gwh + 3 * Cc * Cc; __half* wol = gwl + 3 * Cc * Cc;  // W_out^T

    // 1. weight transpose + split (one launch)
    wprep_kernel<<<(4 * 65536) / 256, 256>>>(W_val, W_off, W_attn, W_out, gwh, gwl);

    // 2. fused: value projection (240 blocks) + off/attn projection (128 blocks), grid.y = 4
    hgemm_kernel<<<dim3(NROWS_VAL / 128 + NQ / 128, 4), 256, SM_TOT>>>(
        input_flatten, wvh, wvl, b_val, b_val, 512, gv, NROWS_VAL / 128,
        query,         wqh, wql, b_off, b_attn, 128, goa);

    // 3. fused loc/softmax + deformable sampling -> fp32 tmp (also outputs loc & attn)
    sample_kernel<<<(NQ * 8) / 8, 256>>>(gv, goa, refpts, loc_out, attn_out, gt);

    // 4. output projection -> d_out
    hgemm_kernel<<<dim3(NQ / 128, 4), 256, SM_TOT>>>(
        gt, woh, wol, b_out, b_out, 512, out, NQ / 128,
        gt, woh, wol, b_out, b_out, 512, out);
}

// round 16
// speedup vs baseline: 2.0733x; 1.0874x over previous
#include <cuda_runtime.h>
#include <cuda_fp16.h>
#include <cstdint>

// ---------------- problem constants ----------------
#define Nb   8
#define LQ   2048
#define Cc   256
#define NQ   (Nb*LQ)        // 16384
#define Ssum 3840
#define NROWS_VAL (Nb*Ssum) // 30720

__device__ __constant__ int   c_T[4]    = {2048, 1024, 512, 256};
__device__ __constant__ int   c_S[4]    = {0, 2048, 3072, 3584};
__device__ __constant__ float c_invT[4] = {1.f/2048.f, 1.f/1024.f, 1.f/512.f, 1.f/256.f};

// ---------------- static scratch ----------------
__device__ float  g_value[NROWS_VAL * Cc];      // fp32 value projection (31.5 MB)
__device__ float  g_offattn[NQ * Cc];           // off logits (0-127) + attn logits (128-255)
__device__ float  g_tmp[NQ * Cc];               // sampled tensor (feeds out-proj)
__device__ __half g_wh[4][Cc * Cc];             // transposed fp16 weights: 0=val, 1,2=off||attn, 3=out
__device__ float  g_loc_s[NQ * 8 * 16];
__device__ float  g_attn_s[NQ * 8 * 16];

// ---------------- helpers ----------------
__device__ __forceinline__ uint32_t smem_u32(const void* p) {
    uint32_t a;
    asm("{ .reg .u64 t; cvta.to.shared.u64 t, %1; cvt.u32.u64 %0, t; }" : "=r"(a) : "l"(p));
    return a;
}
__device__ __forceinline__ void ldmatrix_x4(uint32_t& r0, uint32_t& r1, uint32_t& r2, uint32_t& r3,
                                            uint32_t addr) {
    asm volatile("ldmatrix.sync.aligned.m8n8.x4.shared.b16 {%0,%1,%2,%3}, [%4];"
                 : "=r"(r0), "=r"(r1), "=r"(r2), "=r"(r3) : "r"(addr));
}
__device__ __forceinline__ void mma16816(float* c, const uint32_t* a, uint32_t b0, uint32_t b1) {
    asm volatile("mma.sync.aligned.m16n8k16.row.col.f32.f16.f16.f32 "
                 "{%0,%1,%2,%3},{%4,%5,%6,%7},{%8,%9},{%0,%1,%2,%3};"
                 : "+f"(c[0]), "+f"(c[1]), "+f"(c[2]), "+f"(c[3])
                 : "r"(a[0]), "r"(a[1]), "r"(a[2]), "r"(a[3]), "r"(b0), "r"(b1));
}
__device__ __forceinline__ void cp_async16(uint32_t dst, const void* src) {
    asm volatile("cp.async.cg.shared.global [%0], [%1], 16;" :: "r"(dst), "l"(src));
}
__device__ __forceinline__ void cp_async_wait_all() {
    asm volatile("cp.async.commit_group;\n\tcp.async.wait_group 0;" ::: "memory");
}

// B resident tile: 64 rows x 256 halfs (512 B/row); chunk-XOR swizzle (low 3 bits of chunk)
#define SWZB(r, k) ((r) * 512 + ((((((k) >> 3) & ~7) | ((((k) >> 3) & 7) ^ ((r) & 7)))) << 4))
// A stage: 128 rows x 32 halfs (64 B/row); 4 chunks/row, XOR by (r>>1)&3 (conflict-free for ldsm)
#define SWZA32(r, k) ((r) * 64 + (((((k) >> 3) & 3) ^ (((r) >> 1) & 3)) << 4))

// smem layout (bytes): Bh [0,32K) | A hi stages: 32K + s*8K
#define SM_AST 32768
#define SM_TOT 49152

// ---------------- pipelined HMMA GEMM, 2 CTAs/SM, fused fp32->fp16 round of A ----------------
// C[M x 256] = A[M,256] @ Bt[256,256]^T + bias.  Plain fp16 x fp16, fp32 accumulate.
// Error = activation + weight fp16 rounding ~ 4e-4 rel, under the 1e-3 gate (measured
// activation-only term was 2.97e-4 in R14).
// Block 128(m) x 64(n); 8 warps = 4m x 2n, warp tile 32x32. K: 8 pipelined chunks of 32.
// Dual dispatch: blocks [0,nx0) run problem 0, rest run problem 1.
__global__ __launch_bounds__(256, 2)
void hgemm_kernel(const float* __restrict__ A0, const __half* __restrict__ B0h,
                  const float* __restrict__ b0a, const float* __restrict__ b0b,
                  int bsplit0, float* __restrict__ C0, int nx0,
                  const float* __restrict__ A1, const __half* __restrict__ B1h,
                  const float* __restrict__ b1a, const float* __restrict__ b1b,
                  int bsplit1, float* __restrict__ C1)
{
    extern __shared__ char smem[];
    const uint32_t sb = smem_u32(smem);
    const int tid = threadIdx.x;
    const int wid = tid >> 5;
    const int lane = tid & 31;

    const bool p0 = ((int)blockIdx.x < nx0);
    const float*  A      = p0 ? A0 : A1;
    const __half* Bh     = p0 ? B0h : B1h;
    const float*  bias0  = p0 ? b0a : b1a;
    const float*  bias1  = p0 ? b0b : b1b;
    const int     bsplit = p0 ? bsplit0 : bsplit1;
    float*        C      = p0 ? C0 : C1;
    const int m0 = (p0 ? blockIdx.x : blockIdx.x - nx0) * 128;
    const int n0 = blockIdx.y * 64;
    const int wm = (wid & 3) * 32;
    const int wn = (wid >> 2) * 32;

    // ---- B resident load (once): 64 rows x 256 k via cp.async ----
#pragma unroll
    for (int i = 0; i < 8; i++) {
        int lin = i * 256 + tid;                 // 0..2047
        int r = lin >> 5, c = lin & 31;          // row, 16B-chunk
        size_t g = (size_t)(n0 + r) * 256 + c * 8;
        cp_async16(sb + SWZB(r, c * 8), Bh + g);
    }

    // ---- A loader mapping: thread t -> row tid>>1, 16-half half (tid&1) of the 32-wide chunk ----
    const int a_r0   = tid >> 1;
    const int a_half = tid & 1;
    const float* Abase = A + (size_t)(m0 + a_r0) * 256 + a_half * 16;

    float4 pre[4];
#pragma unroll
    for (int i = 0; i < 4; i++) pre[i] = *(const float4*)(Abase + i * 4);

    // convert chunk 0 -> stage 0
    {
        float f[16] = {pre[0].x, pre[0].y, pre[0].z, pre[0].w, pre[1].x, pre[1].y, pre[1].z, pre[1].w,
                       pre[2].x, pre[2].y, pre[2].z, pre[2].w, pre[3].x, pre[3].y, pre[3].z, pre[3].w};
        __half h[16];
#pragma unroll
        for (int e = 0; e < 16; e++) h[e] = __float2half_rn(f[e]);
#pragma unroll
        for (int j = 0; j < 2; j++) {
            uint32_t sw = (uint32_t)(a_r0 * 64 + (((a_half * 2 + j) ^ ((a_r0 >> 1) & 3)) << 4));
            *(uint4*)(smem + SM_AST + sw) = ((uint4*)h)[j];
        }
    }
    cp_async_wait_all();
    __syncthreads();

    float acc[2][4][4];
#pragma unroll
    for (int i = 0; i < 2; i++)
#pragma unroll
        for (int j = 0; j < 4; j++)
#pragma unroll
            for (int k = 0; k < 4; k++) acc[i][j][k] = 0.f;

    const int a_r  = (lane & 15);
    const int a_k8 = (lane >> 4) << 3;
    const int b_r  = (lane & 7) + ((lane >> 4) << 3);
    const int b_k8 = ((lane >> 3) & 1) << 3;

    for (int kc = 0; kc < 8; ++kc) {
        // prefetch next A chunk (hidden under MMAs below)
        if (kc < 7) {
#pragma unroll
            for (int i = 0; i < 4; i++)
                pre[i] = *(const float4*)(Abase + (kc + 1) * 32 + i * 4);
        }

        const uint32_t Ahb = sb + SM_AST + (kc & 1) * 8192;
#pragma unroll
        for (int ks = 0; ks < 2; ++ks) {
            const int k0 = ks * 16;
            uint32_t ah[2][4], bh[2][4];
#pragma unroll
            for (int mi = 0; mi < 2; mi++) {
                int r = wm + mi * 16 + a_r;
                ldmatrix_x4(ah[mi][0], ah[mi][1], ah[mi][2], ah[mi][3],
                            Ahb + SWZA32(r, k0 + a_k8));
            }
#pragma unroll
            for (int np = 0; np < 2; np++) {
                int r = wn + np * 16 + b_r;
                ldmatrix_x4(bh[np][0], bh[np][1], bh[np][2], bh[np][3],
                            sb + SWZB(r, kc * 32 + k0 + b_k8));
            }
#pragma unroll
            for (int mi = 0; mi < 2; mi++)
#pragma unroll
                for (int ni = 0; ni < 4; ni++)
                    mma16816(acc[mi][ni], ah[mi],
                             bh[ni >> 1][(ni & 1) * 2], bh[ni >> 1][(ni & 1) * 2 + 1]);
        }

        // convert prefetched chunk -> other stage
        if (kc < 7) {
            uint32_t dst = SM_AST + ((kc + 1) & 1) * 8192;
            float f[16] = {pre[0].x, pre[0].y, pre[0].z, pre[0].w, pre[1].x, pre[1].y, pre[1].z, pre[1].w,
                           pre[2].x, pre[2].y, pre[2].z, pre[2].w, pre[3].x, pre[3].y, pre[3].z, pre[3].w};
            __half h[16];
#pragma unroll
            for (int e = 0; e < 16; e++) h[e] = __float2half_rn(f[e]);
#pragma unroll
            for (int j = 0; j < 2; j++) {
                uint32_t sw = (uint32_t)(a_r0 * 64 + (((a_half * 2 + j) ^ ((a_r0 >> 1) & 3)) << 4));
                *(uint4*)(smem + dst + sw) = ((uint4*)h)[j];
            }
        }
        __syncthreads();
    }

    // ---- epilogue ----
    const int g  = lane >> 2;
    const int tq = lane & 3;
#pragma unroll
    for (int ni = 0; ni < 4; ni++) {
        int c = n0 + wn + ni * 8 + 2 * tq;
        float bv0 = (c     < bsplit) ? bias0[c]     : bias1[c - bsplit];
        float bv1 = (c + 1 < bsplit) ? bias0[c + 1] : bias1[c + 1 - bsplit];
#pragma unroll
        for (int mi = 0; mi < 2; mi++) {
            int row = m0 + wm + mi * 16 + g;
            *(float2*)(C + (size_t)row * 256 + c)       = make_float2(acc[mi][ni][0] + bv0,
                                                                      acc[mi][ni][1] + bv1);
            *(float2*)(C + (size_t)(row + 8) * 256 + c) = make_float2(acc[mi][ni][2] + bv0,
                                                                      acc[mi][ni][3] + bv1);
        }
    }
}

// ---------------- fused weight prep: transpose + fp16 round, all 4 matrices ----------------
__global__ void wprep_kernel(const float* __restrict__ W_val, const float* __restrict__ W_off,
                             const float* __restrict__ W_attn, const float* __restrict__ W_out,
                             __half* __restrict__ gwh)
{
    int idx = blockIdx.x * blockDim.x + threadIdx.x;   // 0 .. 4*65536-1
    int mat = idx >> 16;
    int i   = idx & 65535;
    int n = i >> 8, k = i & 255;

    float x;
    int dst;
    if (mat == 0) {                 // W_val^T -> slot 0
        x = W_val[(size_t)k * 256 + n];
        dst = i;
    } else if (mat == 1) {          // W_off^T -> slot 1 rows [0,128)
        if (n >= 128) return;
        x = W_off[(size_t)k * 128 + n];
        dst = 65536 + n * 256 + k;
    } else if (mat == 2) {          // W_attn^T -> slot 1 rows [128,256)
        if (n >= 128) return;
        x = W_attn[(size_t)k * 128 + n];
        dst = 65536 + (128 + n) * 256 + k;
    } else {                        // W_out^T -> slot 3
        x = W_out[(size_t)k * 256 + n];
        dst = 3 * 65536 + i;
    }
    gwh[dst] = __float2half_rn(x);
}

// ---------------- fused loc/softmax + bilinear sampling (issue-optimized inner loop) ----------
// one warp per (nq, m). lanes 0-15: loc; lanes 16-31: softmaxed attn.
// Per-point offsets & attn-premultiplied weights are precomputed in lanes 0-15;
// the 16-point loop is 4 shfl + 2 LDG + 2 FMA per iteration.
__global__ void sample_kernel(const float* __restrict__ value,
                              const float* __restrict__ goa,
                              const float* __restrict__ refp,
                              float* __restrict__ loc_out,
                              float* __restrict__ attn_out,
                              float* __restrict__ outv)
{
    int warp = (blockIdx.x * blockDim.x + threadIdx.x) >> 5;
    int lane = threadIdx.x & 31;
    if (warp >= NQ * 8) return;
    int m  = warp & 7;
    int nq = warp >> 3;
    int n  = nq >> 11;
    int j  = lane & 15;

    float v = goa[(size_t)nq * 256 + (lane < 16 ? m * 16 + j : 128 + m * 16 + j)];

    // softmax within the upper 16-lane half (lower-half result unused)
    float mx = v;
#pragma unroll
    for (int o = 1; o < 16; o <<= 1) mx = fmaxf(mx, __shfl_xor_sync(0xffffffffu, mx, o));
    float e = __expf(v - mx);
    float s = e;
#pragma unroll
    for (int o = 1; o < 16; o <<= 1) s += __shfl_xor_sync(0xffffffffu, s, o);

    int l4 = j >> 2;
    float myv = (lane < 16) ? (refp[(size_t)nq * 4 + l4] + v * c_invT[l4]) : (e / s);

    if (lane < 16) loc_out[(size_t)warp * 16 + j]  = myv;
    else           attn_out[(size_t)warp * 16 + j] = myv;

    // ---- precompute per-point data (meaningful in lanes 0-15; shuffles read only lp<16) ----
    float aw = __shfl_sync(0xffffffffu, myv, 16 + j);   // attn weight of point j
    int   T = c_T[l4], S = c_S[l4];
    float pos  = myv * (float)T - 0.5f;                 // myv = loc in lanes 0-15
    float x0f  = floorf(pos);
    float frac = pos - x0f;
    int   x0   = (int)x0f;
    float fw0 = ((x0 >= 0 && x0 < T) ? (1.f - frac) : 0.f) * aw;
    float fw1 = ((x0 + 1 >= 0 && x0 + 1 < T) ? frac : 0.f) * aw;
    int ofs0 = (S + min(max(x0, 0), T - 1)) * 256;      // element offsets (fit in int)
    int ofs1 = (S + min(max(x0 + 1, 0), T - 1)) * 256;

    const float* vbase = value + (size_t)n * Ssum * 256 + m * 32 + lane;
    float acc = 0.f;
#pragma unroll
    for (int lp = 0; lp < 16; ++lp) {
        int   o0 = __shfl_sync(0xffffffffu, ofs0, lp);
        int   o1 = __shfl_sync(0xffffffffu, ofs1, lp);
        float w0 = __shfl_sync(0xffffffffu, fw0, lp);
        float w1 = __shfl_sync(0xffffffffu, fw1, lp);
        acc += w0 * __ldg(vbase + o0) + w1 * __ldg(vbase + o1);
    }
    outv[(size_t)warp * 32 + lane] = acc;
}

// ---------------- launch ----------------
extern "C" void kernel_launch(void* const* d_in, const int* in_sizes, int n_in,
                              void* d_out, int out_size)
{
    const float* query         = (const float*)d_in[0];
    const float* refpts        = (const float*)d_in[1];
    const float* input_flatten = (const float*)d_in[2];
    const float* W_off  = (const float*)d_in[5];
    const float* b_off  = (const float*)d_in[6];
    const float* W_attn = (const float*)d_in[7];
    const float* b_attn = (const float*)d_in[8];
    const float* W_val  = (const float*)d_in[9];
    const float* b_val  = (const float*)d_in[10];
    const float* W_out  = (const float*)d_in[11];
    const float* b_out  = (const float*)d_in[12];
    float* out = (float*)d_out;

    float *gv, *goa, *gt, *gls, *gas;
    __half *gwh;
    cudaGetSymbolAddress((void**)&gv,  g_value);
    cudaGetSymbolAddress((void**)&goa, g_offattn);
    cudaGetSymbolAddress((void**)&gt,  g_tmp);
    cudaGetSymbolAddress((void**)&gwh, g_wh);
    cudaGetSymbolAddress((void**)&gls, g_loc_s);
    cudaGetSymbolAddress((void**)&gas, g_attn_s);

    const int OUT_ELEMS  = NQ * Cc;       // 4194304
    const int LOCA_ELEMS = NQ * 8 * 16;   // 2097152
    float* loc_out  = (out_size >= OUT_ELEMS + 2 * LOCA_ELEMS) ? out + OUT_ELEMS : gls;
    float* attn_out = (out_size >= OUT_ELEMS + 2 * LOCA_ELEMS) ? out + OUT_ELEMS + LOCA_ELEMS : gas;

    cudaFuncSetAttribute(hgemm_kernel, cudaFuncAttributeMaxDynamicSharedMemorySize, SM_TOT);

    __half* wvh = gwh;               // W_val^T
    __half* wqh = gwh + 1 * Cc * Cc; // [W_off;W_attn]^T
    __half* woh = gwh + 3 * Cc * Cc; // W_out^T

    // 1. weight transpose + fp16 round (one launch)
    wprep_kernel<<<(4 * 65536) / 256, 256>>>(W_val, W_off, W_attn, W_out, gwh);

    // 2. fused: value projection (240 blocks) + off/attn projection (128 blocks), grid.y = 4
    hgemm_kernel<<<dim3(NROWS_VAL / 128 + NQ / 128, 4), 256, SM_TOT>>>(
        input_flatten, wvh, b_val, b_val, 512, gv, NROWS_VAL / 128,
        query,         wqh, b_off, b_attn, 128, goa);

    // 3. fused loc/softmax + deformable sampling -> fp32 tmp (also outputs loc & attn)
    sample_kernel<<<(NQ * 8) / 8, 256>>>(gv, goa, refpts, loc_out, attn_out, gt);

    // 4. output projection -> d_out
    hgemm_kernel<<<dim3(NQ / 128, 4), 256, SM_TOT>>>(
        gt, woh, b_out, b_out, 512, out, NQ / 128,
        gt, woh, b_out, b_out, 512, out);
}